// round 3
// baseline (speedup 1.0000x reference)
#include <cuda_runtime.h>
#include <cstdint>

#define IN_F   4096
#define OUT_F  4096
#define M_ROWS 8192
#define NNZ_C  75008

// ---- scratch (static device globals; no allocation APIs allowed) ----
__device__ __align__(256) float g_W[(size_t)OUT_F * IN_F];   // 64 MB dequantized weight
__device__ __align__(256) float g_x[(size_t)M_ROWS * IN_F];  // 128 MB tf32-rounded activations

// ---------------------------------------------------------------------------
// helpers
// ---------------------------------------------------------------------------
__device__ __forceinline__ float tf32r(float f) {
    uint32_t u;
    asm("cvt.rna.tf32.f32 %0, %1;" : "=r"(u) : "f"(f));
    return __uint_as_float(u);
}

__device__ __forceinline__ void cp16(uint32_t s, const float* g) {
    asm volatile("cp.async.cg.shared.global [%0], [%1], 16;\n" :: "r"(s), "l"(g));
}

// ---------------------------------------------------------------------------
// 1) round x -> tf32 (so GEMM mainloop has no CVTs; mma truncation is exact)
// ---------------------------------------------------------------------------
__global__ void round_x_kernel(const float* __restrict__ x) {
    size_t i = ((size_t)blockIdx.x * blockDim.x + threadIdx.x) * 4;
    float4 v = *(const float4*)(x + i);
    v.x = tf32r(v.x); v.y = tf32r(v.y); v.z = tf32r(v.z); v.w = tf32r(v.w);
    *(float4*)(g_x + i) = v;
}

// ---------------------------------------------------------------------------
// 2) dequant: one thread per packed int32 -> 8 weights of one output channel
//    qweight[p][o], nibble j -> W[o][p*8+j] = lut[o][nib]
// ---------------------------------------------------------------------------
__global__ void dequant_kernel(const int* __restrict__ qw, const float* __restrict__ lut) {
    int t = blockIdx.x * blockDim.x + threadIdx.x;    // 0 .. 2M-1
    int o = t & (OUT_F - 1);
    int p = t >> 12;
    unsigned q = (unsigned)qw[t];                     // == qw[p*OUT_F + o]
    const float* lrow = lut + (size_t)o * 16;
    float v[8];
#pragma unroll
    for (int j = 0; j < 8; j++) v[j] = lrow[(q >> (4 * j)) & 0xF];
    float4* dst = (float4*)(g_W + (size_t)o * IN_F + p * 8);
    dst[0] = make_float4(v[0], v[1], v[2], v[3]);
    dst[1] = make_float4(v[4], v[5], v[6], v[7]);
}

// ---------------------------------------------------------------------------
// 3) CSR outlier scatter-add. Row id j via searchsorted(rows, j, 'right')-1,
//    clipped — exactly the reference semantics.
// ---------------------------------------------------------------------------
__global__ void outlier_kernel(const int* __restrict__ rows, const int* __restrict__ cols,
                               const float* __restrict__ vals) {
    int j = blockIdx.x * blockDim.x + threadIdx.x;
    if (j >= NNZ_C) return;
    int lo = 0, hi = OUT_F + 1;                       // rows has OUT_F+1 entries
    while (lo < hi) {
        int mid = (lo + hi) >> 1;
        if (rows[mid] <= j) lo = mid + 1; else hi = mid;
    }
    int o = lo - 1;
    if (o < 0) o = 0;
    if (o > OUT_F - 1) o = OUT_F - 1;
    atomicAdd(&g_W[(size_t)o * IN_F + cols[j]], vals[j]);
}

// ---------------------------------------------------------------------------
// 4) round W -> tf32 in place (after outliers, matching reference order)
// ---------------------------------------------------------------------------
__global__ void round_w_kernel() {
    size_t i = ((size_t)blockIdx.x * blockDim.x + threadIdx.x) * 4;
    float4 v = *(float4*)(g_W + i);
    v.x = tf32r(v.x); v.y = tf32r(v.y); v.z = tf32r(v.z); v.w = tf32r(v.w);
    *(float4*)(g_W + i) = v;
}

// ---------------------------------------------------------------------------
// 5) GEMM: y[M,N] = x[M,K] * W[N,K]^T + bias, tf32 mma.sync m16n8k8
//    128x128x16 CTA tile, 256 threads, 8 warps of 64x32, cp.async double buffer.
// ---------------------------------------------------------------------------
#define BM 128
#define BN 128
#define BK 16
#define SA 20   // padded smem stride: (20g+tg) mod 32 hits all 32 banks -> conflict-free

__global__ __launch_bounds__(256, 1) void gemm_kernel(const float* __restrict__ bias,
                                                      float* __restrict__ y) {
    __shared__ float As[2][BM * SA];
    __shared__ float Bs[2][BN * SA];

    const int tid  = threadIdx.x;
    const int bm   = blockIdx.y * BM;
    const int bn   = blockIdx.x * BN;
    const int warp = tid >> 5;
    const int lane = tid & 31;
    const int wm   = (warp & 1) * 64;   // 2 warps along M
    const int wn   = (warp >> 1) * 32;  // 4 warps along N
    const int g    = lane >> 2;         // groupID
    const int tg   = lane & 3;          // threadID_in_group

    // gmem->smem tiling: 512 float4 chunks per operand, 2 per thread
    const int lrow = tid >> 2;
    const int lcol = (tid & 3) * 4;
    const float* Ag  = g_x + (size_t)(bm + lrow) * IN_F + lcol;
    const float* Ag2 = Ag + (size_t)64 * IN_F;
    const float* Bg  = g_W + (size_t)(bn + lrow) * IN_F + lcol;
    const float* Bg2 = Bg + (size_t)64 * IN_F;

    uint32_t sA  = (uint32_t)__cvta_generic_to_shared(&As[0][lrow * SA + lcol]);
    uint32_t sA2 = (uint32_t)__cvta_generic_to_shared(&As[0][(lrow + 64) * SA + lcol]);
    uint32_t sB  = (uint32_t)__cvta_generic_to_shared(&Bs[0][lrow * SA + lcol]);
    uint32_t sB2 = (uint32_t)__cvta_generic_to_shared(&Bs[0][(lrow + 64) * SA + lcol]);
    const uint32_t bufBytes = BM * SA * 4;

    float acc[4][4][4];
#pragma unroll
    for (int a = 0; a < 4; a++)
#pragma unroll
        for (int b = 0; b < 4; b++)
#pragma unroll
            for (int c = 0; c < 4; c++) acc[a][b][c] = 0.f;

    // prologue: tile 0 -> buf 0
    cp16(sA, Ag); cp16(sA2, Ag2); cp16(sB, Bg); cp16(sB2, Bg2);
    asm volatile("cp.async.commit_group;\n" ::: "memory");

    const int NK = IN_F / BK;
#pragma unroll 1
    for (int kt = 0; kt < NK; kt++) {
        asm volatile("cp.async.wait_group 0;\n" ::: "memory");
        __syncthreads();
        if (kt + 1 < NK) {
            const int k0 = (kt + 1) * BK;
            const uint32_t off = ((kt + 1) & 1) * bufBytes;
            cp16(sA + off, Ag + k0);
            cp16(sA2 + off, Ag2 + k0);
            cp16(sB + off, Bg + k0);
            cp16(sB2 + off, Bg2 + k0);
            asm volatile("cp.async.commit_group;\n" ::: "memory");
        }
        const float* A = As[kt & 1];
        const float* B = Bs[kt & 1];
#pragma unroll
        for (int kk = 0; kk < BK; kk += 8) {
            uint32_t af[4][4], bf[4][2];
#pragma unroll
            for (int mi = 0; mi < 4; mi++) {
                int r = wm + mi * 16 + g;
                af[mi][0] = __float_as_uint(A[r * SA + kk + tg]);
                af[mi][1] = __float_as_uint(A[(r + 8) * SA + kk + tg]);
                af[mi][2] = __float_as_uint(A[r * SA + kk + tg + 4]);
                af[mi][3] = __float_as_uint(A[(r + 8) * SA + kk + tg + 4]);
            }
#pragma unroll
            for (int ni = 0; ni < 4; ni++) {
                int c = wn + ni * 8 + g;
                bf[ni][0] = __float_as_uint(B[c * SA + kk + tg]);
                bf[ni][1] = __float_as_uint(B[c * SA + kk + tg + 4]);
            }
#pragma unroll
            for (int mi = 0; mi < 4; mi++)
#pragma unroll
                for (int ni = 0; ni < 4; ni++)
                    asm volatile(
                        "mma.sync.aligned.m16n8k8.row.col.f32.tf32.tf32.f32 "
                        "{%0,%1,%2,%3}, {%4,%5,%6,%7}, {%8,%9}, {%0,%1,%2,%3};\n"
                        : "+f"(acc[mi][ni][0]), "+f"(acc[mi][ni][1]),
                          "+f"(acc[mi][ni][2]), "+f"(acc[mi][ni][3])
                        : "r"(af[mi][0]), "r"(af[mi][1]), "r"(af[mi][2]), "r"(af[mi][3]),
                          "r"(bf[ni][0]), "r"(bf[ni][1]));
        }
    }

    // epilogue: c0/c1 -> (row g, cols 2tg,2tg+1); c2/c3 -> row g+8
#pragma unroll
    for (int mi = 0; mi < 4; mi++) {
        int r = bm + wm + mi * 16 + g;
#pragma unroll
        for (int ni = 0; ni < 4; ni++) {
            int c = bn + wn + ni * 8 + tg * 2;
            float b0 = bias[c], b1 = bias[c + 1];
            float2 v0 = make_float2(acc[mi][ni][0] + b0, acc[mi][ni][1] + b1);
            float2 v1 = make_float2(acc[mi][ni][2] + b0, acc[mi][ni][3] + b1);
            *(float2*)(y + (size_t)r * OUT_F + c) = v0;
            *(float2*)(y + (size_t)(r + 8) * OUT_F + c) = v1;
        }
    }
}

// ---------------------------------------------------------------------------
// launch
// ---------------------------------------------------------------------------
extern "C" void kernel_launch(void* const* d_in, const int* in_sizes, int n_in,
                              void* d_out, int out_size) {
    const float* x     = (const float*)d_in[0];
    const float* lut   = (const float*)d_in[1];
    const float* bias  = (const float*)d_in[2];
    const float* ovals = (const float*)d_in[3];
    const int*   qw    = (const int*)d_in[4];
    const int*   orows = (const int*)d_in[5];
    const int*   ocols = (const int*)d_in[6];
    float* y = (float*)d_out;

    round_x_kernel<<<(M_ROWS * IN_F / 4) / 256, 256>>>(x);            // 32768 blocks
    dequant_kernel<<<(IN_F / 8) * OUT_F / 256, 256>>>(qw, lut);        // 8192 blocks
    outlier_kernel<<<(NNZ_C + 255) / 256, 256>>>(orows, ocols, ovals); // 294 blocks
    round_w_kernel<<<(OUT_F * IN_F / 4) / 256, 256>>>();               // 16384 blocks

    dim3 grid(OUT_F / BN, M_ROWS / BM);                                // 32 x 64
    gemm_kernel<<<grid, 256>>>(bias, y);
}

// round 12
// speedup vs baseline: 1.1179x; 1.1179x over previous
#include <cuda_runtime.h>
#include <cstdint>

#define IN_F   4096
#define OUT_F  4096
#define M_ROWS 8192
#define NNZ_C  75008

// ---- scratch (static device globals; no allocation APIs allowed) ----
// Both stored K-PERMUTED: within each 16-element k-block, element k sits at
// position (k%4)*4 + (k%16)/4  (4x4 transpose, an involution). This makes the
// mma.m16n8k8 fragment values each thread needs contiguous -> LDS.128.
__device__ __align__(1024) float g_W[(size_t)OUT_F * IN_F];   // 64 MB weight
__device__ __align__(1024) float g_x[(size_t)M_ROWS * IN_F];  // 128 MB activations

// ===========================================================================
// helpers
// ===========================================================================
__device__ __forceinline__ float tf32r(float f) {
    uint32_t u;
    asm("cvt.rna.tf32.f32 %0, %1;" : "=r"(u) : "f"(f));
    return __uint_as_float(u);
}
__device__ __forceinline__ void cp16(uint32_t s, const float* g) {
    asm volatile("cp.async.cg.shared.global [%0], [%1], 16;" :: "r"(s), "l"(g));
}

// ===========================================================================
// 1) round x -> tf32, store k-permuted
// ===========================================================================
__global__ void round_x_kernel(const float* __restrict__ x) {
    size_t base = ((size_t)blockIdx.x * blockDim.x + threadIdx.x) * 4;
    float4 v = *(const float4*)(x + base);
    size_t row = base >> 12;            // / IN_F
    uint32_t k  = (uint32_t)(base & 4095);
    uint32_t blk = k & ~15u;            // 16-block base
    uint32_t t   = (k & 15) >> 2;       // float4 slot within block
    float* dst = g_x + (row << 12) + blk;
    dst[t]      = tf32r(v.x);           // k=blk+4t+0 -> pos 0*4+t
    dst[4 + t]  = tf32r(v.y);           // k=blk+4t+1 -> pos 1*4+t
    dst[8 + t]  = tf32r(v.z);
    dst[12 + t] = tf32r(v.w);
}

// ===========================================================================
// 2) dequant: one thread per packed int32 -> 8 weights (k-permuted store)
// ===========================================================================
__global__ void dequant_kernel(const int* __restrict__ qw, const float* __restrict__ lut) {
    int t = blockIdx.x * blockDim.x + threadIdx.x;     // 0 .. 2M-1
    int o = t & (OUT_F - 1);
    int p = t >> 12;                                   // packed row 0..511
    unsigned q = (unsigned)qw[t];
    const float* lrow = lut + (size_t)o * 16;
    int blk  = (p >> 1) << 4;                          // 16-block base (k = 8p..8p+7)
    int odd2 = (p & 1) * 2;                            // k%16 = 8*(p&1)+j
    float* dst = g_W + (size_t)o * IN_F + blk;
#pragma unroll
    for (int j = 0; j < 8; j++)
        dst[((j & 3) << 2) + odd2 + (j >> 2)] = lrow[(q >> (4 * j)) & 0xF];
}

// ===========================================================================
// 3) CSR outlier scatter-add (column index permuted to match storage)
// ===========================================================================
__global__ void outlier_kernel(const int* __restrict__ rows, const int* __restrict__ cols,
                               const float* __restrict__ vals) {
    int j = blockIdx.x * blockDim.x + threadIdx.x;
    if (j >= NNZ_C) return;
    int lo = 0, hi = OUT_F + 1;
    while (lo < hi) {
        int mid = (lo + hi) >> 1;
        if (rows[mid] <= j) lo = mid + 1; else hi = mid;
    }
    int o = lo - 1;
    if (o < 0) o = 0;
    if (o > OUT_F - 1) o = OUT_F - 1;
    int c = cols[j];
    int pos = (c & ~15) + ((c & 3) << 2) + ((c & 15) >> 2);
    atomicAdd(&g_W[(size_t)o * IN_F + pos], vals[j]);
}

// ===========================================================================
// 4) round W -> tf32 in place (elementwise; permutation-agnostic)
// ===========================================================================
__global__ void round_w_kernel() {
    size_t i = ((size_t)blockIdx.x * blockDim.x + threadIdx.x) * 4;
    float4 v = *(float4*)(g_W + i);
    v.x = tf32r(v.x); v.y = tf32r(v.y); v.z = tf32r(v.z); v.w = tf32r(v.w);
    *(float4*)(g_W + i) = v;
}

// ===========================================================================
// 5) GEMM: y = x @ W^T + bias, tf32 mma.sync m16n8k8
//    CTA 128x256, 8 warps of 64x64, BK=16, 4-stage cp.async, LDS.128 frags.
// ===========================================================================
#define BM 128
#define BN 256
#define BK 16
#define PITCH 20                        // floats per row slot (80 B) -> conflict-free
#define NSTG 4
#define NK (IN_F / BK)                  // 256
#define STG ((BM + BN) * PITCH)         // 7680 floats per stage
#define SMEM_BYTES (NSTG * STG * 4)     // 122880 B

__global__ __launch_bounds__(256, 1) void gemm_kernel(const float* __restrict__ bias,
                                                      float* __restrict__ y) {
    extern __shared__ float sm[];
    const uint32_t smb = (uint32_t)__cvta_generic_to_shared(sm);

    const int tid  = threadIdx.x;
    const int warp = tid >> 5;
    const int lane = tid & 31;
    const int g    = lane >> 2;
    const int tg   = lane & 3;
    const int wm   = (warp & 1) * 64;
    const int wn   = (warp >> 1) * 64;
    const int bm   = blockIdx.y * BM;
    const int bn   = blockIdx.x * BN;

    // cp.async assignments: A = 512 x 16B chunks, B = 1024 x 16B chunks
    const float* aS[2]; uint32_t aD[2];
#pragma unroll
    for (int i = 0; i < 2; i++) {
        int id = i * 256 + tid, row = id >> 2, c = id & 3;
        aS[i] = g_x + (size_t)(bm + row) * IN_F + c * 4;
        aD[i] = smb + (uint32_t)(row * PITCH + c * 4) * 4;
    }
    const float* bS[4]; uint32_t bD[4];
#pragma unroll
    for (int i = 0; i < 4; i++) {
        int id = i * 256 + tid, row = id >> 2, c = id & 3;
        bS[i] = g_W + (size_t)(bn + row) * IN_F + c * 4;
        bD[i] = smb + (uint32_t)((BM + row) * PITCH + c * 4) * 4;
    }

    float acc[4][8][4];
#pragma unroll
    for (int mi = 0; mi < 4; mi++)
#pragma unroll
        for (int ni = 0; ni < 8; ni++)
#pragma unroll
            for (int c = 0; c < 4; c++) acc[mi][ni][c] = 0.f;

    // prologue: fill stages 0..NSTG-2
#pragma unroll
    for (int s = 0; s < NSTG - 1; s++) {
        const uint32_t so = (uint32_t)s * STG * 4;
        const int ko = s * BK;
#pragma unroll
        for (int i = 0; i < 2; i++) cp16(aD[i] + so, aS[i] + ko);
#pragma unroll
        for (int i = 0; i < 4; i++) cp16(bD[i] + so, bS[i] + ko);
        asm volatile("cp.async.commit_group;" ::: "memory");
    }

#pragma unroll 1
    for (int kt = 0; kt < NK; kt++) {
        asm volatile("cp.async.wait_group %0;" :: "n"(NSTG - 2) : "memory");
        __syncthreads();

        // prefetch stage kt+NSTG-1 (writes a stage last read at iter kt-1)
        if (kt + NSTG - 1 < NK) {
            const uint32_t so = (uint32_t)((kt + NSTG - 1) & (NSTG - 1)) * STG * 4;
            const int ko = (kt + NSTG - 1) * BK;
#pragma unroll
            for (int i = 0; i < 2; i++) cp16(aD[i] + so, aS[i] + ko);
#pragma unroll
            for (int i = 0; i < 4; i++) cp16(bD[i] + so, bS[i] + ko);
            asm volatile("cp.async.commit_group;" ::: "memory");
        }

        const float* A = sm + (kt & (NSTG - 1)) * STG;
        const float* B = A + BM * PITCH;

        // fragment loads: k-permuted layout -> float4 = {k=tg, tg+4, tg+8, tg+12}
        float4 av[4][2], bv[8];
#pragma unroll
        for (int mi = 0; mi < 4; mi++) {
            av[mi][0] = *(const float4*)(A + (wm + mi * 16 + g) * PITCH + tg * 4);
            av[mi][1] = *(const float4*)(A + (wm + mi * 16 + 8 + g) * PITCH + tg * 4);
        }
#pragma unroll
        for (int ni = 0; ni < 8; ni++)
            bv[ni] = *(const float4*)(B + (wn + ni * 8 + g) * PITCH + tg * 4);

        // kk = 0..7:  a = {av0.x, av1.x, av0.y, av1.y}, b = {bv.x, bv.y}
#pragma unroll
        for (int mi = 0; mi < 4; mi++)
#pragma unroll
            for (int ni = 0; ni < 8; ni++)
                asm volatile(
                    "mma.sync.aligned.m16n8k8.row.col.f32.tf32.tf32.f32 "
                    "{%0,%1,%2,%3}, {%4,%5,%6,%7}, {%8,%9}, {%0,%1,%2,%3};"
                    : "+f"(acc[mi][ni][0]), "+f"(acc[mi][ni][1]),
                      "+f"(acc[mi][ni][2]), "+f"(acc[mi][ni][3])
                    : "r"(__float_as_uint(av[mi][0].x)), "r"(__float_as_uint(av[mi][1].x)),
                      "r"(__float_as_uint(av[mi][0].y)), "r"(__float_as_uint(av[mi][1].y)),
                      "r"(__float_as_uint(bv[ni].x)),    "r"(__float_as_uint(bv[ni].y)));
        // kk = 8..15: a = {av0.z, av1.z, av0.w, av1.w}, b = {bv.z, bv.w}
#pragma unroll
        for (int mi = 0; mi < 4; mi++)
#pragma unroll
            for (int ni = 0; ni < 8; ni++)
                asm volatile(
                    "mma.sync.aligned.m16n8k8.row.col.f32.tf32.tf32.f32 "
                    "{%0,%1,%2,%3}, {%4,%5,%6,%7}, {%8,%9}, {%0,%1,%2,%3};"
                    : "+f"(acc[mi][ni][0]), "+f"(acc[mi][ni][1]),
                      "+f"(acc[mi][ni][2]), "+f"(acc[mi][ni][3])
                    : "r"(__float_as_uint(av[mi][0].z)), "r"(__float_as_uint(av[mi][1].z)),
                      "r"(__float_as_uint(av[mi][0].w)), "r"(__float_as_uint(av[mi][1].w)),
                      "r"(__float_as_uint(bv[ni].z)),    "r"(__float_as_uint(bv[ni].w)));
    }

    // epilogue: c0/c1 -> (row g, cols 2tg,2tg+1); c2/c3 -> row g+8
#pragma unroll
    for (int mi = 0; mi < 4; mi++) {
        const int r = bm + wm + mi * 16 + g;
#pragma unroll
        for (int ni = 0; ni < 8; ni++) {
            const int c = bn + wn + ni * 8 + tg * 2;
            const float b0 = __ldg(bias + c), b1 = __ldg(bias + c + 1);
            *(float2*)(y + (size_t)r * OUT_F + c) =
                make_float2(acc[mi][ni][0] + b0, acc[mi][ni][1] + b1);
            *(float2*)(y + (size_t)(r + 8) * OUT_F + c) =
                make_float2(acc[mi][ni][2] + b0, acc[mi][ni][3] + b1);
        }
    }
}

// ===========================================================================
// launch
// ===========================================================================
extern "C" void kernel_launch(void* const* d_in, const int* in_sizes, int n_in,
                              void* d_out, int out_size) {
    const float* x     = (const float*)d_in[0];
    const float* lut   = (const float*)d_in[1];
    const float* bias  = (const float*)d_in[2];
    const float* ovals = (const float*)d_in[3];
    const int*   qw    = (const int*)d_in[4];
    const int*   orows = (const int*)d_in[5];
    const int*   ocols = (const int*)d_in[6];
    float* y = (float*)d_out;

    round_x_kernel<<<(M_ROWS * IN_F / 4) / 256, 256>>>(x);
    dequant_kernel<<<(IN_F / 8) * OUT_F / 256, 256>>>(qw, lut);
    outlier_kernel<<<(NNZ_C + 255) / 256, 256>>>(orows, ocols, ovals);
    round_w_kernel<<<(OUT_F * IN_F / 4) / 256, 256>>>();

    cudaFuncSetAttribute(gemm_kernel, cudaFuncAttributeMaxDynamicSharedMemorySize, SMEM_BYTES);
    dim3 grid(OUT_F / BN, M_ROWS / BM);   // 16 x 64 = 1024 CTAs
    gemm_kernel<<<grid, 256, SMEM_BYTES>>>(bias, y);
}